// round 1
// baseline (speedup 1.0000x reference)
#include <cuda_runtime.h>

#define BB 8
#define CC 256
#define HH 96
#define WW 96
#define HW (HH*WW)          // 9216
#define PATCH 21
#define HALFP 10
#define DILP 2

// Scratch for D = sum_c in1*in2 : B*H*W floats = 1.18 MB (fits L2 easily)
__device__ float g_D[BB * HW];

// ---------------------------------------------------------------------------
// Kernel 1: channel dot product.
// Block = 256 threads = 32 lanes (float4 across W => 128 spatial/block)
//                     x 8 channel-groups (32 channels each).
// Grid  = B*HW / 128 = 576 blocks. Each block stays inside one batch b
// (9216 % 128 == 0).
// ---------------------------------------------------------------------------
__global__ void __launch_bounds__(256) dot_kernel(const float* __restrict__ a,
                                                  const float* __restrict__ b) {
    __shared__ float4 red[256];

    const int tid  = threadIdx.x;
    const int lane = tid & 31;        // 0..31 : float4 spatial lane
    const int cg   = tid >> 5;        // 0..7  : channel group

    // Spatial base for this block (in floats): 128 consecutive positions.
    const long long sbase = (long long)blockIdx.x * 128;
    const int bidx = (int)(sbase / HW);
    const int hw   = (int)(sbase % HW) + lane * 4;

    const float4* __restrict__ A =
        (const float4*)(a + (size_t)bidx * CC * HW + hw);
    const float4* __restrict__ Bp =
        (const float4*)(b + (size_t)bidx * CC * HW + hw);

    const int cstride = HW / 4;       // float4 stride between channels = 2304
    const int c0 = cg * 32;

    float4 acc = make_float4(0.f, 0.f, 0.f, 0.f);
    #pragma unroll 8
    for (int c = 0; c < 32; ++c) {
        const size_t off = (size_t)(c0 + c) * cstride;
        float4 x = A[off];
        float4 y = Bp[off];
        acc.x = fmaf(x.x, y.x, acc.x);
        acc.y = fmaf(x.y, y.y, acc.y);
        acc.z = fmaf(x.z, y.z, acc.z);
        acc.w = fmaf(x.w, y.w, acc.w);
    }

    red[tid] = acc;
    __syncthreads();

    if (tid < 32) {
        float4 r = red[tid];
        #pragma unroll
        for (int k = 1; k < 8; ++k) {
            float4 t = red[tid + 32 * k];
            r.x += t.x; r.y += t.y; r.z += t.z; r.w += t.w;
        }
        ((float4*)g_D)[(size_t)blockIdx.x * 32 + tid] = r;
    }
}

// ---------------------------------------------------------------------------
// Kernel 2: gather / shift-replicate.
// One float4 output store per thread. Output layout: (B, 441, 96, 96).
// Source offsets are even (dilation 2) -> in-bounds fast path uses two
// aligned float2 loads from L2-resident g_D.
// Total float4s: 8*441*96*24 = 8,128,512 -> 31752 blocks x 256.
// ---------------------------------------------------------------------------
__global__ void __launch_bounds__(256) gather_kernel(float* __restrict__ out) {
    const int idx = blockIdx.x * 256 + threadIdx.x;

    int x4 = idx % 24;
    int t  = idx / 24;
    int y  = t % HH;   t /= HH;
    int p  = t % (PATCH * PATCH);
    int b  = t / (PATCH * PATCH);

    const int py = p / PATCH;
    const int px = p % PATCH;

    const int sy    = y + (py - HALFP) * DILP;
    const int xbase = x4 * 4 + (px - HALFP) * DILP;   // even

    float4 v = make_float4(0.f, 0.f, 0.f, 0.f);

    if ((unsigned)sy < (unsigned)HH) {
        const float* __restrict__ row = g_D + ((size_t)b * HH + sy) * WW;
        if (xbase >= 0 && xbase + 3 < WW) {
            // fast path: two 8B-aligned float2 loads
            float2 lo = *(const float2*)(row + xbase);
            float2 hi = *(const float2*)(row + xbase + 2);
            v.x = lo.x; v.y = lo.y; v.z = hi.x; v.w = hi.y;
        } else {
            int x0 = xbase;
            if ((unsigned)x0       < (unsigned)WW) v.x = row[x0];
            if ((unsigned)(x0 + 1) < (unsigned)WW) v.y = row[x0 + 1];
            if ((unsigned)(x0 + 2) < (unsigned)WW) v.z = row[x0 + 2];
            if ((unsigned)(x0 + 3) < (unsigned)WW) v.w = row[x0 + 3];
        }
    }

    ((float4*)out)[idx] = v;
}

extern "C" void kernel_launch(void* const* d_in, const int* in_sizes, int n_in,
                              void* d_out, int out_size) {
    const float* in1 = (const float*)d_in[0];
    const float* in2 = (const float*)d_in[1];
    float* out = (float*)d_out;

    // Kernel 1: B*HW / 128 = 576 blocks
    dot_kernel<<<(BB * HW) / 128, 256>>>(in1, in2);

    // Kernel 2: B*441*96*24 float4 = 8,128,512 / 256 = 31752 blocks
    gather_kernel<<<(BB * PATCH * PATCH * HH * (WW / 4)) / 256, 256>>>(out);
}